// round 10
// baseline (speedup 1.0000x reference)
#include <cuda_runtime.h>
#include <cuda_fp16.h>
#include <cstdint>
#include <cstddef>

// ---------------- problem constants ----------------
constexpr int BB   = 8;
constexpr int TT   = 16;
constexpr int HID  = 64;
constexpr int NPIX = 1024;

// ---------------- step-kernel smem layout (uint32 words) ----------------
// Bh: word = hx*36 + cc*8 + kc*2 + h   (hx = halo px 0..379, 10 rows x 38 cols)
constexpr int BH_PXSTR = 36;                  // 32 data + 4 pad -> conflict-free LDS.128
constexpr int BH_W     = 380 * BH_PXSTR;      // 13680
constexpr int BX_OFF   = BH_W;                // Bx: [400 px][2 words] (380 real + pad)
constexpr int BX_W     = 800;
constexpr int AR_OFF   = BX_OFF + BX_W;       // 14480
constexpr int GROUP_W  = 4 * 1024;            // 4 chunks per group
constexpr int AR_W     = 3 * GROUP_W;         // 12288
constexpr int SMEM_W   = AR_OFF + AR_W;       // 26768
constexpr size_t SMEM_STEP = (size_t)SMEM_W * 4;   // 107072 B (x2 CTAs <= 228KB)
constexpr int SGST = 132;                     // epilogue gate staging stride (floats)

// chunk stream: 0..12 input (13..15 zero pad), 16.. hidden (16 + j*4 + kc)
constexpr int NG_FULL = 53;                   // 4 input groups + 49 hidden groups
constexpr int G_HID0  = 4;

// tap pixel offsets: poff[j] = (j/7)*38 + j%7
__device__ __constant__ int c_poff[52] = {
      0,  1,  2,  3,  4,  5,  6,
     38, 39, 40, 41, 42, 43, 44,
     76, 77, 78, 79, 80, 81, 82,
    114,115,116,117,118,119,120,
    152,153,154,155,156,157,158,
    190,191,192,193,194,195,196,
    228,229,230,231,232,233,234,
    266,267,268};

// ---------------- device scratch ----------------
__device__ uint32_t g_hp[2][(size_t)16 * 32 * NPIX];   // packed fp16 hidden (half2 ci-pairs)
__device__ float    g_c[(size_t)16 * HID * NPIX];      // cell state fp32
__device__ uint32_t g_wS[(size_t)4 * 240 * 1024];      // unified A chunk stream

// ---------------- helpers ----------------
__device__ __forceinline__ uint32_t smem_u32(const void* p) {
    uint32_t a;
    asm("{ .reg .u64 t; cvta.to.shared.u64 t, %1; cvt.u32.u64 %0, t; }" : "=r"(a) : "l"(p));
    return a;
}
__device__ __forceinline__ void mma_f16(float* c, const uint32_t* a,
                                        uint32_t b0, uint32_t b1) {
    asm volatile(
        "mma.sync.aligned.m16n8k16.row.col.f32.f16.f16.f32 "
        "{%0,%1,%2,%3}, {%4,%5,%6,%7}, {%8,%9}, {%0,%1,%2,%3};"
        : "+f"(c[0]), "+f"(c[1]), "+f"(c[2]), "+f"(c[3])
        : "r"(a[0]), "r"(a[1]), "r"(a[2]), "r"(a[3]), "r"(b0), "r"(b1));
}
__device__ __forceinline__ void cp16(uint32_t dst, const void* src) {
    asm volatile("cp.async.cg.shared.global [%0], [%1], 16;" :: "r"(dst), "l"(src));
}
__device__ __forceinline__ void cp4(uint32_t dst, const void* src) {
    asm volatile("cp.async.ca.shared.global [%0], [%1], 4;" :: "r"(dst), "l"(src));
}
__device__ __forceinline__ void cp_commit() {
    asm volatile("cp.async.commit_group;" ::: "memory");
}
__device__ __forceinline__ void cp_wait0() {
    asm volatile("cp.async.wait_group 0;" ::: "memory");
}
__device__ __forceinline__ void cp_wait1() {
    asm volatile("cp.async.wait_group 1;" ::: "memory");
}
__device__ __forceinline__ void cp_wait2() {
    asm volatile("cp.async.wait_group 2;" ::: "memory");
}
__device__ __forceinline__ uint32_t packh2(float lo, float hi) {
    __half2 h = __floats2half2_rn(lo, hi);
    return *(uint32_t*)&h;
}
__device__ __forceinline__ float sigf(float x) {
    return __fdividef(1.0f, 1.0f + __expf(-x));
}
__device__ __forceinline__ float tanh_fast(float x) {
    return __fdividef(2.0f, 1.0f + __expf(-2.0f * x)) - 1.0f;
}

// ---------------------------------------------------------------------------
// Kernel 0: build unified A chunk stream. grid 848 = dm(4) x chunk(212).
// Chunks 0..12 input (13..15 zero), 16+j*4+kc hidden.
// ---------------------------------------------------------------------------
__global__ void prep_w_kernel(const float* __restrict__ wihf, const float* __restrict__ whhf,
                              const float* __restrict__ wihb, const float* __restrict__ whhb)
{
    int bid  = blockIdx.x;
    int c    = bid % 212;
    int dm   = bid / 212;
    int mblk = dm & 1, dir = dm >> 1;
    const float* wih = dir ? wihb : wihf;
    const float* whh = dir ? whhb : whhf;
    uint32_t* dst = g_wS + ((size_t)dm * 240 + c) * 1024;

    for (int i = threadIdx.x; i < 1024; i += 256) {
        int reg  = i & 3;
        int lane = (i >> 2) & 31;
        int mt   = i >> 7;
        int m    = mt * 16 + (lane >> 2) + (reg & 1) * 8;
        int co   = (m >> 5) * 64 + mblk * 32 + (m & 31);
        float lo = 0.0f, hi = 0.0f;
        if (c < 13) {                     // input chunks
            int pair = c * 8 + (lane & 3) + (reg >> 1) * 4;
            int j = pair >> 1, cip = pair & 1;
            if (j < 49) {
                int ky = j / 7, kx = j - ky * 7;
                int ci0 = cip * 2;
                lo = wih[((size_t)co * 3 + ci0) * 49 + ky * 7 + kx];
                if (ci0 + 1 < 3)
                    hi = wih[((size_t)co * 3 + ci0 + 1) * 49 + ky * 7 + kx];
            }
        } else if (c >= 16) {             // hidden chunks
            int hc = c - 16;
            int j = hc >> 2, kc = hc & 3;
            if (j < 49) {
                int ky = j / 7, kx = j - ky * 7;
                int k = kc * 16 + (lane & 3) * 2 + (reg >> 1) * 8;
                lo = whh[((size_t)co * HID + k)     * 49 + ky * 7 + kx];
                hi = whh[((size_t)co * HID + k + 1) * 49 + ky * 7 + kx];
            }
        }
        dst[i] = packh2(lo, hi);
    }
}

// ---------------------------------------------------------------------------
// Kernel 1: fully-fused recurrence step.
// grid 256 = rb(8) x mblk(2) x n(8) x dir(2); 256 threads; 2 CTAs/SM.
// Stream order: input groups (0..3) first, Bh staged asynchronously under them.
// ---------------------------------------------------------------------------
__global__ void __launch_bounds__(256, 2)
lstm_step(const float* __restrict__ x,
          const float* __restrict__ bf, const float* __restrict__ bb,
          float* __restrict__ out, int t)
{
    extern __shared__ char smem[];
    uint32_t* smw = (uint32_t*)smem;
    uint32_t  sb  = smem_u32(smem);

    int tid = threadIdx.x, wid = tid >> 5, lane = tid & 31;
    int rr = lane >> 2, cc = lane & 3;
    int wm = wid & 1, wn = wid >> 1;          // wn = output row 0..3

    int bid  = blockIdx.x;
    int rb   = bid & 7;
    int mblk = (bid >> 3) & 1;
    int n    = (bid >> 4) & 7;
    int dir  = (bid >> 7) & 1;
    int y0   = rb * 4;
    int dm   = dir * 2 + mblk;
    int dn   = dir * BB + n;
    int tcur = dir ? (TT - 1 - t) : t;

    const uint32_t* hpin  = g_hp[t & 1]       + (size_t)dn * 32 * NPIX;
    uint32_t*       hpout = g_hp[(t & 1) ^ 1] + (size_t)dn * 32 * NPIX;
    float*          cbuf  = g_c               + (size_t)dn * HID * NPIX;
    const float*    bias  = dir ? bb : bf;
    const float*    xin   = x + (size_t)(n * TT + tcur) * 3 * NPIX;

    int nG = (t > 0) ? NG_FULL : 4;
    auto cpS = [&](int g, int buf) {
        int cb = (g < G_HID0) ? g * 4 : 16 + (g - G_HID0) * 4;
        const float4* src = (const float4*)(g_wS + ((size_t)dm * 240 + cb) * 1024);
        uint32_t dstb = sb + (uint32_t)(AR_OFF + buf * GROUP_W) * 4;
        #pragma unroll
        for (int u = 0; u < 4; u++)
            cp16(dstb + (uint32_t)(u * 256 + tid) * 16, src + u * 256 + tid);
    };
    // G0 = A group 0, G1 = A group 1 (input chunks -> available immediately)
    cpS(0, 0); cp_commit();
    cpS(1, 1); cp_commit();

    float acc[4][4][4];
    #pragma unroll
    for (int ms = 0; ms < 4; ms++)
        #pragma unroll
        for (int ns = 0; ns < 4; ns++)
            #pragma unroll
            for (int q = 0; q < 4; q++) acc[ms][ns][q] = 0.0f;

    // ---- stage Bx synchronously: 10x38 halo of x (+zero pad to px 400) ----
    #pragma unroll
    for (int i = 0; i < 2; i++) {
        int px = tid + i * 256;
        if (px < 400) {
            float v0 = 0, v1 = 0, v2 = 0;
            if (px < 380) {
                int row = px / 38, col = px - row * 38;
                int y = y0 - 3 + row, xx = col - 3;
                if ((unsigned)y < 32u && (unsigned)xx < 32u) {
                    int o = y * 32 + xx;
                    v0 = xin[o]; v1 = xin[NPIX + o]; v2 = xin[2 * NPIX + o];
                }
            }
            smw[BX_OFF + px * 2]     = packh2(v0, v1);
            smw[BX_OFF + px * 2 + 1] = packh2(v2, 0.0f);
        }
    }

    // ---- G2 = Bh async staging (t>0): cp.async 4B scatter, zero STS for oob ----
    if (t > 0) {
        int q = tid >> 4, t16 = tid & 15;
        int offa = (q & 3) * 8 + (q >> 3) * 2 + ((q >> 2) & 1);   // q = kc*8+cc+4h
        const uint32_t* s0 = hpin + (size_t)q * NPIX;
        const uint32_t* s1 = hpin + (size_t)(q + 16) * NPIX;
        #pragma unroll 4
        for (int i = 0; i < 24; i++) {
            int hx = t16 + i * 16;
            if (hx < 380) {
                int row = hx / 38, col = hx - row * 38;
                int y = y0 - 3 + row, xx = col - 3;
                uint32_t d0 = sb + (uint32_t)(hx * BH_PXSTR + offa) * 4;
                if ((unsigned)y < 32u && (unsigned)xx < 32u) {
                    int o = y * 32 + xx;
                    cp4(d0,      s0 + o);
                    cp4(d0 + 16, s1 + o);
                } else {
                    smw[hx * BH_PXSTR + offa]     = 0;
                    smw[hx * BH_PXSTR + offa + 4] = 0;
                }
            }
        }
    }
    cp_commit();   // G2 (empty for t=0; keeps group accounting uniform)

    int issued = 2;                       // A groups issued
    int pbh = wn * 38 + rr;               // halo pixel base
    int bxb = BX_OFF + pbh * 2 + (cc & 1);

    for (int gi = 0; gi < nG; gi++) {
        if (gi < 2) cp_wait2();
        else if (gi < nG - 1) cp_wait1();
        else cp_wait0();
        __syncthreads();
        if (issued < nG) { cpS(issued, issued % 3); cp_commit(); issued++; }

        const uint32_t* Ab = smw + AR_OFF + (gi % 3) * GROUP_W + wm * 512 + lane * 4;

        if (gi >= G_HID0) {
            // ---- hidden group: one tap j, 4 kc chunks ----
            int j = gi - G_HID0;
            int base = (pbh + c_poff[j]) * BH_PXSTR + cc * 8;
            uint4 b0[4], b1[4];
            #pragma unroll
            for (int ns = 0; ns < 4; ns++) {
                b0[ns] = *(const uint4*)(smw + base + ns * (8 * BH_PXSTR));
                b1[ns] = *(const uint4*)(smw + base + ns * (8 * BH_PXSTR) + 4);
            }
            #pragma unroll
            for (int kc = 0; kc < 4; kc++) {
                #pragma unroll
                for (int ms = 0; ms < 4; ms++) {
                    uint4 a4 = *(const uint4*)(Ab + kc * 1024 + ms * 128);
                    #pragma unroll
                    for (int ns = 0; ns < 4; ns++) {
                        uint32_t w0, w1;
                        if (kc == 0)      { w0 = b0[ns].x; w1 = b0[ns].y; }
                        else if (kc == 1) { w0 = b0[ns].z; w1 = b0[ns].w; }
                        else if (kc == 2) { w0 = b1[ns].x; w1 = b1[ns].y; }
                        else              { w0 = b1[ns].z; w1 = b1[ns].w; }
                        mma_f16(acc[ms][ns], (const uint32_t*)&a4, w0, w1);
                    }
                }
            }
        } else {
            // ---- input group: chunks ic = gi*4+u, cnt real (13 total) ----
            int icb = gi * 4;
            int cnt = 13 - icb; if (cnt > 4) cnt = 4;
            for (int u = 0; u < cnt; u++) {
                int ic = icb + u;
                int jb = ic * 4 + (cc >> 1);
                int o1 = bxb + c_poff[jb] * 2;
                int o2 = bxb + c_poff[jb + 2] * 2;
                uint32_t b[4][2];
                #pragma unroll
                for (int ns = 0; ns < 4; ns++) {
                    b[ns][0] = smw[o1 + ns * 16];
                    b[ns][1] = smw[o2 + ns * 16];
                }
                #pragma unroll
                for (int ms = 0; ms < 4; ms++) {
                    uint4 a4 = *(const uint4*)(Ab + u * 1024 + ms * 128);
                    #pragma unroll
                    for (int ns = 0; ns < 4; ns++)
                        mma_f16(acc[ms][ns], (const uint32_t*)&a4, b[ns][0], b[ns][1]);
                }
            }
        }
    }
    __syncthreads();

    // ---- acc -> s_g gate staging ----
    float* sg = (float*)smem;
    #pragma unroll
    for (int ms = 0; ms < 4; ms++) {
        int m = wm * 64 + ms * 16 + rr;
        #pragma unroll
        for (int ns = 0; ns < 4; ns++) {
            int nn = wn * 32 + ns * 8 + 2 * cc;
            *(float2*)(sg + m * SGST + nn)       = make_float2(acc[ms][ns][0], acc[ms][ns][1]);
            *(float2*)(sg + (m + 8) * SGST + nn) = make_float2(acc[ms][ns][2], acc[ms][ns][3]);
        }
    }
    __syncthreads();

    // ---- LSTM epilogue: thread = (hid pair, 8 px), all vector ops ----
    int hl2 = tid >> 4;                   // 0..15 pair index
    int px0 = (tid & 15) * 8;             // 0..120
    int qout = mblk * 16 + hl2;
    int yx0  = y0 * 32 + px0;

    float hn2[2][8];
    #pragma unroll
    for (int e = 0; e < 2; e++) {
        int hl  = 2 * hl2 + e;
        int ch  = mblk * 32 + hl;
        float bi  = bias[0 * HID + ch];
        float bfg = bias[1 * HID + ch];
        float bg  = bias[2 * HID + ch];
        float bo  = bias[3 * HID + ch];
        const float* rI = sg + (0 * 32 + hl) * SGST + px0;
        const float* rF = sg + (1 * 32 + hl) * SGST + px0;
        const float* rG = sg + (2 * 32 + hl) * SGST + px0;
        const float* rO = sg + (3 * 32 + hl) * SGST + px0;
        float* cp_ptr = cbuf + (size_t)ch * NPIX + yx0;
        float* op     = out + ((size_t)((n * TT + tcur) * 2 * HID) + dir * HID + ch) * NPIX + yx0;
        #pragma unroll
        for (int v = 0; v < 2; v++) {
            float4 gI = *(const float4*)(rI + v * 4);
            float4 gF = *(const float4*)(rF + v * 4);
            float4 gG = *(const float4*)(rG + v * 4);
            float4 gO = *(const float4*)(rO + v * 4);
            float4 cv = make_float4(0, 0, 0, 0);
            if (t > 0) cv = *(const float4*)(cp_ptr + v * 4);
            float ig[4] = {gI.x + bi,  gI.y + bi,  gI.z + bi,  gI.w + bi};
            float fg[4] = {gF.x + bfg, gF.y + bfg, gF.z + bfg, gF.w + bfg};
            float gg[4] = {gG.x + bg,  gG.y + bg,  gG.z + bg,  gG.w + bg};
            float og[4] = {gO.x + bo,  gO.y + bo,  gO.z + bo,  gO.w + bo};
            float cold[4] = {cv.x, cv.y, cv.z, cv.w};
            float4 cnew, hnew;
            float* cn4 = (float*)&cnew;
            float* hn4 = (float*)&hnew;
            #pragma unroll
            for (int p = 0; p < 4; p++) {
                float cn = sigf(fg[p]) * cold[p] + sigf(ig[p]) * tanh_fast(gg[p]);
                float hn = sigf(og[p]) * tanh_fast(cn);
                cn4[p] = cn;
                hn4[p] = hn;
                hn2[e][v * 4 + p] = hn;
            }
            *(float4*)(cp_ptr + v * 4) = cnew;
            *(float4*)(op + v * 4)     = hnew;
        }
    }
    // packed fp16 h write (B-ready ci-pair words)
    uint32_t hw[8];
    #pragma unroll
    for (int p = 0; p < 8; p++) hw[p] = packh2(hn2[0][p], hn2[1][p]);
    uint32_t* hp = hpout + (size_t)qout * NPIX + yx0;
    *(uint4*)(hp)     = *(uint4*)(hw);
    *(uint4*)(hp + 4) = *(uint4*)(hw + 4);
}

// ---------------------------------------------------------------------------
extern "C" void kernel_launch(void* const* d_in, const int* in_sizes, int n_in,
                              void* d_out, int out_size)
{
    const float* x      = (const float*)d_in[0];
    const float* w_ih_f = (const float*)d_in[1];
    const float* w_hh_f = (const float*)d_in[2];
    const float* b_f    = (const float*)d_in[3];
    const float* w_ih_b = (const float*)d_in[4];
    const float* w_hh_b = (const float*)d_in[5];
    const float* b_b    = (const float*)d_in[6];
    float* out = (float*)d_out;

    cudaFuncSetAttribute(lstm_step, cudaFuncAttributeMaxDynamicSharedMemorySize,
                         (int)SMEM_STEP);

    prep_w_kernel<<<848, 256>>>(w_ih_f, w_hh_f, w_ih_b, w_hh_b);
    for (int t = 0; t < TT; t++)
        lstm_step<<<256, 256, SMEM_STEP>>>(x, b_f, b_b, out, t);
}

// round 12
// speedup vs baseline: 1.1470x; 1.1470x over previous
#include <cuda_runtime.h>
#include <cuda_fp16.h>
#include <cstdint>
#include <cstddef>

// ---------------- problem constants ----------------
constexpr int BB   = 8;
constexpr int TT   = 16;
constexpr int HID  = 64;
constexpr int NPIX = 1024;

// ---------------- step-kernel smem layout (uint32 words) ----------------
// Bh: word = hx*36 + cc*8 + kc*2 + h   (hx = halo px 0..379, 10 rows x 38 cols)
constexpr int BH_PXSTR = 36;                  // 32 data + 4 pad -> conflict-free LDS.128
constexpr int BH_W     = 380 * BH_PXSTR;      // 13680
constexpr int BX_OFF   = BH_W;                // Bx: [416 px][2 words] (380 real + zero pad)
constexpr int BX_PX    = 416;                 // covers max overread px 413 (zero-weight taps)
constexpr int BX_W     = BX_PX * 2;           // 832
constexpr int SGST     = 132;                 // epilogue gate staging stride (floats)
constexpr int SG_W     = 128 * SGST;          // 16896 (aliases Bh+Bx)
constexpr int SMEM_W   = SG_W;                // 16896 words
constexpr size_t SMEM_STEP = (size_t)SMEM_W * 4;   // 67584 B (x2 CTAs fits easily)

// chunk stream: 0..12 input (13..15 zero pad), 16.. hidden (16 + j*4 + kc)
constexpr int NG_FULL = 53;                   // 4 input groups + 49 hidden groups
constexpr int G_HID0  = 4;

// tap pixel offsets: poff[j] = (j/7)*38 + j%7
__device__ __constant__ int c_poff[52] = {
      0,  1,  2,  3,  4,  5,  6,
     38, 39, 40, 41, 42, 43, 44,
     76, 77, 78, 79, 80, 81, 82,
    114,115,116,117,118,119,120,
    152,153,154,155,156,157,158,
    190,191,192,193,194,195,196,
    228,229,230,231,232,233,234,
    266,267,268};

// ---------------- device scratch ----------------
__device__ uint32_t g_hp[2][(size_t)16 * 32 * NPIX];   // packed fp16 hidden (half2 ci-pairs)
__device__ float    g_c[(size_t)16 * HID * NPIX];      // cell state fp32
__device__ uint32_t g_wS[(size_t)4 * 240 * 1024];      // unified A chunk stream (frag order)

// ---------------- helpers ----------------
__device__ __forceinline__ void mma_f16(float* c, const uint32_t* a,
                                        uint32_t b0, uint32_t b1) {
    asm volatile(
        "mma.sync.aligned.m16n8k16.row.col.f32.f16.f16.f32 "
        "{%0,%1,%2,%3}, {%4,%5,%6,%7}, {%8,%9}, {%0,%1,%2,%3};"
        : "+f"(c[0]), "+f"(c[1]), "+f"(c[2]), "+f"(c[3])
        : "r"(a[0]), "r"(a[1]), "r"(a[2]), "r"(a[3]), "r"(b0), "r"(b1));
}
__device__ __forceinline__ uint32_t packh2(float lo, float hi) {
    __half2 h = __floats2half2_rn(lo, hi);
    return *(uint32_t*)&h;
}
__device__ __forceinline__ float sigf(float x) {
    return __fdividef(1.0f, 1.0f + __expf(-x));
}
__device__ __forceinline__ float tanh_fast(float x) {
    return __fdividef(2.0f, 1.0f + __expf(-2.0f * x)) - 1.0f;
}

// ---------------------------------------------------------------------------
// Kernel 0: build unified A chunk stream. grid 848 = dm(4) x chunk(212).
// Chunks 0..12 input (13..15 zero), 16+j*4+kc hidden. Fragment order:
// word i = [mt(8)][lane(32)][reg(4)]; m = mt*16+(lane>>2)+(reg&1)*8.
// ---------------------------------------------------------------------------
__global__ void prep_w_kernel(const float* __restrict__ wihf, const float* __restrict__ whhf,
                              const float* __restrict__ wihb, const float* __restrict__ whhb)
{
    int bid  = blockIdx.x;
    int c    = bid % 212;
    int dm   = bid / 212;
    int mblk = dm & 1, dir = dm >> 1;
    const float* wih = dir ? wihb : wihf;
    const float* whh = dir ? whhb : whhf;
    uint32_t* dst = g_wS + ((size_t)dm * 240 + c) * 1024;

    for (int i = threadIdx.x; i < 1024; i += 256) {
        int reg  = i & 3;
        int lane = (i >> 2) & 31;
        int mt   = i >> 7;
        int m    = mt * 16 + (lane >> 2) + (reg & 1) * 8;
        int co   = (m >> 5) * 64 + mblk * 32 + (m & 31);
        float lo = 0.0f, hi = 0.0f;
        if (c < 13) {                     // input chunks
            int pair = c * 8 + (lane & 3) + (reg >> 1) * 4;
            int j = pair >> 1, cip = pair & 1;
            if (j < 49) {
                int ky = j / 7, kx = j - ky * 7;
                int ci0 = cip * 2;
                lo = wih[((size_t)co * 3 + ci0) * 49 + ky * 7 + kx];
                if (ci0 + 1 < 3)
                    hi = wih[((size_t)co * 3 + ci0 + 1) * 49 + ky * 7 + kx];
            }
        } else if (c >= 16) {             // hidden chunks
            int hc = c - 16;
            int j = hc >> 2, kc = hc & 3;
            if (j < 49) {
                int ky = j / 7, kx = j - ky * 7;
                int k = kc * 16 + (lane & 3) * 2 + (reg >> 1) * 8;
                lo = whh[((size_t)co * HID + k)     * 49 + ky * 7 + kx];
                hi = whh[((size_t)co * HID + k + 1) * 49 + ky * 7 + kx];
            }
        }
        dst[i] = packh2(lo, hi);
    }
}

// ---------------------------------------------------------------------------
// Kernel 1: fully-fused recurrence step; barrier-free mainloop.
// A fragments read directly from global (L1/L2-hot); B from smem.
// grid 256 = rb(8) x mblk(2) x n(8) x dir(2); 256 threads; 2 CTAs/SM.
// ---------------------------------------------------------------------------
__global__ void __launch_bounds__(256, 2)
lstm_step(const float* __restrict__ x,
          const float* __restrict__ bf, const float* __restrict__ bb,
          float* __restrict__ out, int t)
{
    extern __shared__ char smem[];
    uint32_t* smw = (uint32_t*)smem;

    int tid = threadIdx.x, wid = tid >> 5, lane = tid & 31;
    int rr = lane >> 2, cc = lane & 3;
    int wm = wid & 1, wn = wid >> 1;          // wn = output row 0..3

    int bid  = blockIdx.x;
    int rb   = bid & 7;
    int mblk = (bid >> 3) & 1;
    int n    = (bid >> 4) & 7;
    int dir  = (bid >> 7) & 1;
    int y0   = rb * 4;
    int dm   = dir * 2 + mblk;
    int dn   = dir * BB + n;
    int tcur = dir ? (TT - 1 - t) : t;

    const uint32_t* hpin  = g_hp[t & 1]       + (size_t)dn * 32 * NPIX;
    uint32_t*       hpout = g_hp[(t & 1) ^ 1] + (size_t)dn * 32 * NPIX;
    float*          cbuf  = g_c               + (size_t)dn * HID * NPIX;
    const float*    bias  = dir ? bb : bf;
    const float*    xin   = x + (size_t)(n * TT + tcur) * 3 * NPIX;

    // per-thread A fragment base (uint4 units): chunk c at Adm + c*256 + ms*32
    const uint4* Adm = (const uint4*)g_wS + (size_t)dm * 240 * 256 + wm * 128 + lane;

    float acc[4][4][4];
    #pragma unroll
    for (int ms = 0; ms < 4; ms++)
        #pragma unroll
        for (int ns = 0; ns < 4; ns++)
            #pragma unroll
            for (int q = 0; q < 4; q++) acc[ms][ns][q] = 0.0f;

    // ---- stage Bx: 10x38 halo of x, zero-padded out to px 416 ----
    #pragma unroll
    for (int i = 0; i < 2; i++) {
        int px = tid + i * 256;
        if (px < BX_PX) {
            float v0 = 0, v1 = 0, v2 = 0;
            if (px < 380) {
                int row = px / 38, col = px - row * 38;
                int y = y0 - 3 + row, xx = col - 3;
                if ((unsigned)y < 32u && (unsigned)xx < 32u) {
                    int o = y * 32 + xx;
                    v0 = xin[o]; v1 = xin[NPIX + o]; v2 = xin[2 * NPIX + o];
                }
            }
            smw[BX_OFF + px * 2]     = packh2(v0, v1);
            smw[BX_OFF + px * 2 + 1] = packh2(v2, 0.0f);
        }
    }

    // ---- stage Bh (t>0): thread = (q 0..15, t16); planes q and q+16 ----
    if (t > 0) {
        int q = tid >> 4, t16 = tid & 15;
        int offa = (q & 3) * 8 + (q >> 3) * 2 + ((q >> 2) & 1);   // q = kc*8+cc+4h
        const uint32_t* s0 = hpin + (size_t)q * NPIX;
        const uint32_t* s1 = hpin + (size_t)(q + 16) * NPIX;
        #pragma unroll 4
        for (int i = 0; i < 24; i++) {
            int hx = t16 + i * 16;
            if (hx < 380) {
                int row = hx / 38, col = hx - row * 38;
                int y = y0 - 3 + row, xx = col - 3;
                uint32_t w0 = 0, w1 = 0;
                if ((unsigned)y < 32u && (unsigned)xx < 32u) {
                    int o = y * 32 + xx;
                    w0 = s0[o]; w1 = s1[o];
                }
                smw[hx * BH_PXSTR + offa]     = w0;   // kc
                smw[hx * BH_PXSTR + offa + 4] = w1;   // kc+2
            }
        }
    }
    __syncthreads();          // the ONLY pre-loop barrier

    int nG = (t > 0) ? NG_FULL : 4;
    int pbh = wn * 38 + rr;               // halo pixel base
    int bxb = BX_OFF + pbh * 2 + (cc & 1);

    for (int gi = 0; gi < nG; gi++) {
        if (gi >= G_HID0) {
            // ---- hidden group: one tap j, 4 kc chunks; A via direct LDG ----
            int j = gi - G_HID0;
            const uint4* Ag = Adm + (16 + j * 4) * 256;
            int base = (pbh + c_poff[j]) * BH_PXSTR + cc * 8;
            uint4 b0[4], b1[4];
            #pragma unroll
            for (int ns = 0; ns < 4; ns++) {
                b0[ns] = *(const uint4*)(smw + base + ns * (8 * BH_PXSTR));
                b1[ns] = *(const uint4*)(smw + base + ns * (8 * BH_PXSTR) + 4);
            }
            #pragma unroll
            for (int kc = 0; kc < 4; kc++) {
                uint4 a4[4];
                #pragma unroll
                for (int ms = 0; ms < 4; ms++)
                    a4[ms] = __ldg(Ag + kc * 256 + ms * 32);
                #pragma unroll
                for (int ms = 0; ms < 4; ms++) {
                    #pragma unroll
                    for (int ns = 0; ns < 4; ns++) {
                        uint32_t w0, w1;
                        if (kc == 0)      { w0 = b0[ns].x; w1 = b0[ns].y; }
                        else if (kc == 1) { w0 = b0[ns].z; w1 = b0[ns].w; }
                        else if (kc == 2) { w0 = b1[ns].x; w1 = b1[ns].y; }
                        else              { w0 = b1[ns].z; w1 = b1[ns].w; }
                        mma_f16(acc[ms][ns], (const uint32_t*)&a4[ms], w0, w1);
                    }
                }
            }
        } else {
            // ---- input group: chunks ic = gi*4+u, 13 real total ----
            int icb = gi * 4;
            int cnt = 13 - icb; if (cnt > 4) cnt = 4;
            for (int u = 0; u < cnt; u++) {
                int ic = icb + u;
                const uint4* Ag = Adm + ic * 256;
                int jb = ic * 4 + (cc >> 1);
                int o1 = bxb + c_poff[jb] * 2;
                int o2 = bxb + c_poff[jb + 2] * 2;
                uint32_t b[4][2];
                #pragma unroll
                for (int ns = 0; ns < 4; ns++) {
                    b[ns][0] = smw[o1 + ns * 16];
                    b[ns][1] = smw[o2 + ns * 16];
                }
                #pragma unroll
                for (int ms = 0; ms < 4; ms++) {
                    uint4 a4 = __ldg(Ag + ms * 32);
                    #pragma unroll
                    for (int ns = 0; ns < 4; ns++)
                        mma_f16(acc[ms][ns], (const uint32_t*)&a4, b[ns][0], b[ns][1]);
                }
            }
        }
    }
    __syncthreads();

    // ---- acc -> s_g gate staging (aliases Bh/Bx space) ----
    float* sg = (float*)smem;
    #pragma unroll
    for (int ms = 0; ms < 4; ms++) {
        int m = wm * 64 + ms * 16 + rr;
        #pragma unroll
        for (int ns = 0; ns < 4; ns++) {
            int nn = wn * 32 + ns * 8 + 2 * cc;
            *(float2*)(sg + m * SGST + nn)       = make_float2(acc[ms][ns][0], acc[ms][ns][1]);
            *(float2*)(sg + (m + 8) * SGST + nn) = make_float2(acc[ms][ns][2], acc[ms][ns][3]);
        }
    }
    __syncthreads();

    // ---- LSTM epilogue: thread = (hid pair, 8 px), all vector ops ----
    int hl2 = tid >> 4;                   // 0..15 pair index
    int px0 = (tid & 15) * 8;             // 0..120
    int qout = mblk * 16 + hl2;
    int yx0  = y0 * 32 + px0;

    float hn2[2][8];
    #pragma unroll
    for (int e = 0; e < 2; e++) {
        int hl  = 2 * hl2 + e;
        int ch  = mblk * 32 + hl;
        float bi  = bias[0 * HID + ch];
        float bfg = bias[1 * HID + ch];
        float bg  = bias[2 * HID + ch];
        float bo  = bias[3 * HID + ch];
        const float* rI = sg + (0 * 32 + hl) * SGST + px0;
        const float* rF = sg + (1 * 32 + hl) * SGST + px0;
        const float* rG = sg + (2 * 32 + hl) * SGST + px0;
        const float* rO = sg + (3 * 32 + hl) * SGST + px0;
        float* cp_ptr = cbuf + (size_t)ch * NPIX + yx0;
        float* op     = out + ((size_t)((n * TT + tcur) * 2 * HID) + dir * HID + ch) * NPIX + yx0;
        #pragma unroll
        for (int v = 0; v < 2; v++) {
            float4 gI = *(const float4*)(rI + v * 4);
            float4 gF = *(const float4*)(rF + v * 4);
            float4 gG = *(const float4*)(rG + v * 4);
            float4 gO = *(const float4*)(rO + v * 4);
            float4 cv = make_float4(0, 0, 0, 0);
            if (t > 0) cv = *(const float4*)(cp_ptr + v * 4);
            float ig[4] = {gI.x + bi,  gI.y + bi,  gI.z + bi,  gI.w + bi};
            float fg[4] = {gF.x + bfg, gF.y + bfg, gF.z + bfg, gF.w + bfg};
            float gg[4] = {gG.x + bg,  gG.y + bg,  gG.z + bg,  gG.w + bg};
            float og[4] = {gO.x + bo,  gO.y + bo,  gO.z + bo,  gO.w + bo};
            float cold[4] = {cv.x, cv.y, cv.z, cv.w};
            float4 cnew, hnew;
            float* cn4 = (float*)&cnew;
            float* hn4 = (float*)&hnew;
            #pragma unroll
            for (int p = 0; p < 4; p++) {
                float cn = sigf(fg[p]) * cold[p] + sigf(ig[p]) * tanh_fast(gg[p]);
                float hn = sigf(og[p]) * tanh_fast(cn);
                cn4[p] = cn;
                hn4[p] = hn;
                hn2[e][v * 4 + p] = hn;
            }
            *(float4*)(cp_ptr + v * 4) = cnew;
            *(float4*)(op + v * 4)     = hnew;
        }
    }
    // packed fp16 h write (B-ready ci-pair words)
    uint32_t hw[8];
    #pragma unroll
    for (int p = 0; p < 8; p++) hw[p] = packh2(hn2[0][p], hn2[1][p]);
    uint32_t* hp = hpout + (size_t)qout * NPIX + yx0;
    *(uint4*)(hp)     = *(uint4*)(hw);
    *(uint4*)(hp + 4) = *(uint4*)(hw + 4);
}

// ---------------------------------------------------------------------------
extern "C" void kernel_launch(void* const* d_in, const int* in_sizes, int n_in,
                              void* d_out, int out_size)
{
    const float* x      = (const float*)d_in[0];
    const float* w_ih_f = (const float*)d_in[1];
    const float* w_hh_f = (const float*)d_in[2];
    const float* b_f    = (const float*)d_in[3];
    const float* w_ih_b = (const float*)d_in[4];
    const float* w_hh_b = (const float*)d_in[5];
    const float* b_b    = (const float*)d_in[6];
    float* out = (float*)d_out;

    cudaFuncSetAttribute(lstm_step, cudaFuncAttributeMaxDynamicSharedMemorySize,
                         (int)SMEM_STEP);

    prep_w_kernel<<<848, 256>>>(w_ih_f, w_hh_f, w_ih_b, w_hh_b);
    for (int t = 0; t < TT; t++)
        lstm_step<<<256, 256, SMEM_STEP>>>(x, b_f, b_b, out, t);
}

// round 13
// speedup vs baseline: 1.1507x; 1.0032x over previous
#include <cuda_runtime.h>
#include <cuda_fp16.h>
#include <cstdint>
#include <cstddef>

// ---------------- problem constants ----------------
constexpr int BB   = 8;
constexpr int TT   = 16;
constexpr int HID  = 64;
constexpr int NPIX = 1024;

// ---------------- step-kernel smem layout (uint32 words) ----------------
// Bh: word = hx*36 + cc*8 + kc*2 + h   (hx = halo px 0..379, 10 rows x 38 cols)
constexpr int BH_PXSTR = 36;                  // 32 data + 4 pad -> conflict-free LDS.128
constexpr int BH_W     = 380 * BH_PXSTR;      // 13680
constexpr int BX_OFF   = BH_W;                // Bx: [416 px][2 words] (380 real + zero pad)
constexpr int BX_PX    = 416;                 // covers max overread px 413 (zero-weight taps)
constexpr int BX_W     = BX_PX * 2;           // 832
constexpr int SGST     = 132;                 // epilogue gate staging stride (floats)
constexpr int SG_W     = 128 * SGST;          // 16896 (aliases Bh+Bx)
constexpr int SMEM_W   = SG_W;                // 16896 words
constexpr size_t SMEM_STEP = (size_t)SMEM_W * 4;   // 67584 B (x2 CTAs fits)

// chunk stream: 0..12 input (13..15 zero pad), 16.. hidden (16 + j*4 + kc)
constexpr int NG_FULL = 53;                   // 4 input groups + 49 hidden groups
constexpr int G_HID0  = 4;

// tap pixel offsets: poff[j] = (j/7)*38 + j%7
__device__ __constant__ int c_poff[52] = {
      0,  1,  2,  3,  4,  5,  6,
     38, 39, 40, 41, 42, 43, 44,
     76, 77, 78, 79, 80, 81, 82,
    114,115,116,117,118,119,120,
    152,153,154,155,156,157,158,
    190,191,192,193,194,195,196,
    228,229,230,231,232,233,234,
    266,267,268};

// ---------------- device scratch ----------------
__device__ uint32_t g_hp[2][(size_t)16 * 32 * NPIX];   // packed fp16 hidden (half2 ci-pairs)
__device__ float    g_c[(size_t)16 * HID * NPIX];      // cell state fp32
__device__ uint32_t g_wS[(size_t)4 * 240 * 1024];      // unified A chunk stream (frag order)
__device__ int      g_sync[2][8][16];                  // per-(dir,n) step counters

// ---------------- helpers ----------------
__device__ __forceinline__ void mma_f16(float* c, const uint32_t* a,
                                        uint32_t b0, uint32_t b1) {
    asm volatile(
        "mma.sync.aligned.m16n8k16.row.col.f32.f16.f16.f32 "
        "{%0,%1,%2,%3}, {%4,%5,%6,%7}, {%8,%9}, {%0,%1,%2,%3};"
        : "+f"(c[0]), "+f"(c[1]), "+f"(c[2]), "+f"(c[3])
        : "r"(a[0]), "r"(a[1]), "r"(a[2]), "r"(a[3]), "r"(b0), "r"(b1));
}
__device__ __forceinline__ uint32_t packh2(float lo, float hi) {
    __half2 h = __floats2half2_rn(lo, hi);
    return *(uint32_t*)&h;
}
__device__ __forceinline__ float sigf(float x) {
    return __fdividef(1.0f, 1.0f + __expf(-x));
}
__device__ __forceinline__ float tanh_fast(float x) {
    return __fdividef(2.0f, 1.0f + __expf(-2.0f * x)) - 1.0f;
}

// ---------------------------------------------------------------------------
// Kernel 0a: zero the sync counters (graph replays need a fresh state).
// ---------------------------------------------------------------------------
__global__ void zero_sync_kernel() {
    ((int*)g_sync)[threadIdx.x] = 0;      // 256 counters
}

// ---------------------------------------------------------------------------
// Kernel 0b: build unified A chunk stream. grid 848 = dm(4) x chunk(212).
// ---------------------------------------------------------------------------
__global__ void prep_w_kernel(const float* __restrict__ wihf, const float* __restrict__ whhf,
                              const float* __restrict__ wihb, const float* __restrict__ whhb)
{
    int bid  = blockIdx.x;
    int c    = bid % 212;
    int dm   = bid / 212;
    int mblk = dm & 1, dir = dm >> 1;
    const float* wih = dir ? wihb : wihf;
    const float* whh = dir ? whhb : whhf;
    uint32_t* dst = g_wS + ((size_t)dm * 240 + c) * 1024;

    for (int i = threadIdx.x; i < 1024; i += 256) {
        int reg  = i & 3;
        int lane = (i >> 2) & 31;
        int mt   = i >> 7;
        int m    = mt * 16 + (lane >> 2) + (reg & 1) * 8;
        int co   = (m >> 5) * 64 + mblk * 32 + (m & 31);
        float lo = 0.0f, hi = 0.0f;
        if (c < 13) {                     // input chunks
            int pair = c * 8 + (lane & 3) + (reg >> 1) * 4;
            int j = pair >> 1, cip = pair & 1;
            if (j < 49) {
                int ky = j / 7, kx = j - ky * 7;
                int ci0 = cip * 2;
                lo = wih[((size_t)co * 3 + ci0) * 49 + ky * 7 + kx];
                if (ci0 + 1 < 3)
                    hi = wih[((size_t)co * 3 + ci0 + 1) * 49 + ky * 7 + kx];
            }
        } else if (c >= 16) {             // hidden chunks
            int hc = c - 16;
            int j = hc >> 2, kc = hc & 3;
            if (j < 49) {
                int ky = j / 7, kx = j - ky * 7;
                int k = kc * 16 + (lane & 3) * 2 + (reg >> 1) * 8;
                lo = whh[((size_t)co * HID + k)     * 49 + ky * 7 + kx];
                hi = whh[((size_t)co * HID + k + 1) * 49 + ky * 7 + kx];
            }
        }
        dst[i] = packh2(lo, hi);
    }
}

// ---------------------------------------------------------------------------
// Kernel 1: PERSISTENT fused recurrence — all 16 timesteps in one launch.
// grid 256 = rb(8) x mblk(2) x n(8) x dir(2); 256 threads; 2 CTAs/SM (all
// resident; per-(dir,n) atomic counters sync the 16-CTA chain per step).
// ---------------------------------------------------------------------------
__global__ void __launch_bounds__(256, 2)
lstm_persistent(const float* __restrict__ x,
                const float* __restrict__ bf, const float* __restrict__ bb,
                float* __restrict__ out)
{
    extern __shared__ char smem[];
    uint32_t* smw = (uint32_t*)smem;

    int tid = threadIdx.x, wid = tid >> 5, lane = tid & 31;
    int rr = lane >> 2, cc = lane & 3;
    int wm = wid & 1, wn = wid >> 1;          // wn = output row 0..3

    int bid  = blockIdx.x;
    int rb   = bid & 7;
    int mblk = (bid >> 3) & 1;
    int n    = (bid >> 4) & 7;
    int dir  = (bid >> 7) & 1;
    int y0   = rb * 4;
    int dm   = dir * 2 + mblk;
    int dn   = dir * BB + n;

    float*       cbuf = g_c + (size_t)dn * HID * NPIX;
    const float* bias = dir ? bb : bf;

    // per-thread A fragment base (uint4 units): chunk c at Adm + c*256 + ms*32
    const uint4* Adm = (const uint4*)g_wS + (size_t)dm * 240 * 256 + wm * 128 + lane;

    int pbh = wn * 38 + rr;               // halo pixel base
    int bxb = BX_OFF + pbh * 2 + (cc & 1);

    volatile int* syncrow = &g_sync[dir][n][0];

    for (int t = 0; t < TT; t++) {
        int tcur = dir ? (TT - 1 - t) : t;
        const uint32_t* hpin  = g_hp[t & 1]       + (size_t)dn * 32 * NPIX;
        uint32_t*       hpout = g_hp[(t & 1) ^ 1] + (size_t)dn * 32 * NPIX;
        const float*    xin   = x + (size_t)(n * TT + tcur) * 3 * NPIX;

        // ---- wait for chain (dir,n) to finish step t-1 (16 arrivals) ----
        if (t > 0) {
            if (tid == 0) {
                while (syncrow[t - 1] < 16) { }
            }
            __syncthreads();
            __threadfence();   // acquire: h writes from peers now visible
        }

        float acc[4][4][4];
        #pragma unroll
        for (int ms = 0; ms < 4; ms++)
            #pragma unroll
            for (int ns = 0; ns < 4; ns++)
                #pragma unroll
                for (int q = 0; q < 4; q++) acc[ms][ns][q] = 0.0f;

        // ---- stage Bx: 10x38 halo of x, zero-padded out to px 416 ----
        #pragma unroll
        for (int i = 0; i < 2; i++) {
            int px = tid + i * 256;
            if (px < BX_PX) {
                float v0 = 0, v1 = 0, v2 = 0;
                if (px < 380) {
                    int row = px / 38, col = px - row * 38;
                    int y = y0 - 3 + row, xx = col - 3;
                    if ((unsigned)y < 32u && (unsigned)xx < 32u) {
                        int o = y * 32 + xx;
                        v0 = xin[o]; v1 = xin[NPIX + o]; v2 = xin[2 * NPIX + o];
                    }
                }
                smw[BX_OFF + px * 2]     = packh2(v0, v1);
                smw[BX_OFF + px * 2 + 1] = packh2(v2, 0.0f);
            }
        }

        // ---- stage Bh (t>0): thread = (q 0..15, t16); planes q and q+16 ----
        if (t > 0) {
            int q = tid >> 4, t16 = tid & 15;
            int offa = (q & 3) * 8 + (q >> 3) * 2 + ((q >> 2) & 1);  // q = kc*8+cc+4h
            const uint32_t* s0 = hpin + (size_t)q * NPIX;
            const uint32_t* s1 = hpin + (size_t)(q + 16) * NPIX;
            #pragma unroll 4
            for (int i = 0; i < 24; i++) {
                int hx = t16 + i * 16;
                if (hx < 380) {
                    int row = hx / 38, col = hx - row * 38;
                    int y = y0 - 3 + row, xx = col - 3;
                    uint32_t w0 = 0, w1 = 0;
                    if ((unsigned)y < 32u && (unsigned)xx < 32u) {
                        int o = y * 32 + xx;
                        w0 = s0[o]; w1 = s1[o];
                    }
                    smw[hx * BH_PXSTR + offa]     = w0;   // kc
                    smw[hx * BH_PXSTR + offa + 4] = w1;   // kc+2
                }
            }
        }
        __syncthreads();          // staging complete

        int nG = (t > 0) ? NG_FULL : 4;
        for (int gi = 0; gi < nG; gi++) {
            if (gi >= G_HID0) {
                // ---- hidden group: one tap j, 4 kc chunks; A via direct LDG ----
                int j = gi - G_HID0;
                const uint4* Ag = Adm + (16 + j * 4) * 256;
                int base = (pbh + c_poff[j]) * BH_PXSTR + cc * 8;
                uint4 b0[4], b1[4];
                #pragma unroll
                for (int ns = 0; ns < 4; ns++) {
                    b0[ns] = *(const uint4*)(smw + base + ns * (8 * BH_PXSTR));
                    b1[ns] = *(const uint4*)(smw + base + ns * (8 * BH_PXSTR) + 4);
                }
                #pragma unroll
                for (int kc = 0; kc < 4; kc++) {
                    uint4 a4[4];
                    #pragma unroll
                    for (int ms = 0; ms < 4; ms++)
                        a4[ms] = __ldg(Ag + kc * 256 + ms * 32);
                    #pragma unroll
                    for (int ms = 0; ms < 4; ms++) {
                        #pragma unroll
                        for (int ns = 0; ns < 4; ns++) {
                            uint32_t w0, w1;
                            if (kc == 0)      { w0 = b0[ns].x; w1 = b0[ns].y; }
                            else if (kc == 1) { w0 = b0[ns].z; w1 = b0[ns].w; }
                            else if (kc == 2) { w0 = b1[ns].x; w1 = b1[ns].y; }
                            else              { w0 = b1[ns].z; w1 = b1[ns].w; }
                            mma_f16(acc[ms][ns], (const uint32_t*)&a4[ms], w0, w1);
                        }
                    }
                }
            } else {
                // ---- input group: chunks ic = gi*4+u, 13 real total ----
                int icb = gi * 4;
                int cnt = 13 - icb; if (cnt > 4) cnt = 4;
                for (int u = 0; u < cnt; u++) {
                    int ic = icb + u;
                    const uint4* Ag = Adm + ic * 256;
                    int jb = ic * 4 + (cc >> 1);
                    int o1 = bxb + c_poff[jb] * 2;
                    int o2 = bxb + c_poff[jb + 2] * 2;
                    uint32_t b[4][2];
                    #pragma unroll
                    for (int ns = 0; ns < 4; ns++) {
                        b[ns][0] = smw[o1 + ns * 16];
                        b[ns][1] = smw[o2 + ns * 16];
                    }
                    #pragma unroll
                    for (int ms = 0; ms < 4; ms++) {
                        uint4 a4 = __ldg(Ag + ms * 32);
                        #pragma unroll
                        for (int ns = 0; ns < 4; ns++)
                            mma_f16(acc[ms][ns], (const uint32_t*)&a4, b[ns][0], b[ns][1]);
                    }
                }
            }
        }
        __syncthreads();

        // ---- acc -> s_g gate staging (aliases Bh/Bx space) ----
        float* sg = (float*)smem;
        #pragma unroll
        for (int ms = 0; ms < 4; ms++) {
            int m = wm * 64 + ms * 16 + rr;
            #pragma unroll
            for (int ns = 0; ns < 4; ns++) {
                int nn = wn * 32 + ns * 8 + 2 * cc;
                *(float2*)(sg + m * SGST + nn)       = make_float2(acc[ms][ns][0], acc[ms][ns][1]);
                *(float2*)(sg + (m + 8) * SGST + nn) = make_float2(acc[ms][ns][2], acc[ms][ns][3]);
            }
        }
        __syncthreads();

        // ---- LSTM epilogue: thread = (hid pair, 8 px), all vector ops ----
        int hl2 = tid >> 4;                   // 0..15 pair index
        int px0 = (tid & 15) * 8;             // 0..120
        int qout = mblk * 16 + hl2;
        int yx0  = y0 * 32 + px0;

        float hn2[2][8];
        #pragma unroll
        for (int e = 0; e < 2; e++) {
            int hl  = 2 * hl2 + e;
            int ch  = mblk * 32 + hl;
            float bi  = bias[0 * HID + ch];
            float bfg = bias[1 * HID + ch];
            float bg  = bias[2 * HID + ch];
            float bo  = bias[3 * HID + ch];
            const float* rI = sg + (0 * 32 + hl) * SGST + px0;
            const float* rF = sg + (1 * 32 + hl) * SGST + px0;
            const float* rG = sg + (2 * 32 + hl) * SGST + px0;
            const float* rO = sg + (3 * 32 + hl) * SGST + px0;
            float* cp_ptr = cbuf + (size_t)ch * NPIX + yx0;
            float* op     = out + ((size_t)((n * TT + tcur) * 2 * HID) + dir * HID + ch) * NPIX + yx0;
            #pragma unroll
            for (int v = 0; v < 2; v++) {
                float4 gI = *(const float4*)(rI + v * 4);
                float4 gF = *(const float4*)(rF + v * 4);
                float4 gG = *(const float4*)(rG + v * 4);
                float4 gO = *(const float4*)(rO + v * 4);
                float4 cv = make_float4(0, 0, 0, 0);
                if (t > 0) cv = *(const float4*)(cp_ptr + v * 4);
                float ig[4] = {gI.x + bi,  gI.y + bi,  gI.z + bi,  gI.w + bi};
                float fg[4] = {gF.x + bfg, gF.y + bfg, gF.z + bfg, gF.w + bfg};
                float gg[4] = {gG.x + bg,  gG.y + bg,  gG.z + bg,  gG.w + bg};
                float og[4] = {gO.x + bo,  gO.y + bo,  gO.z + bo,  gO.w + bo};
                float cold[4] = {cv.x, cv.y, cv.z, cv.w};
                float4 cnew, hnew;
                float* cn4 = (float*)&cnew;
                float* hn4 = (float*)&hnew;
                #pragma unroll
                for (int p = 0; p < 4; p++) {
                    float cn = sigf(fg[p]) * cold[p] + sigf(ig[p]) * tanh_fast(gg[p]);
                    float hn = sigf(og[p]) * tanh_fast(cn);
                    cn4[p] = cn;
                    hn4[p] = hn;
                    hn2[e][v * 4 + p] = hn;
                }
                *(float4*)(cp_ptr + v * 4) = cnew;
                *(float4*)(op + v * 4)     = hnew;
            }
        }
        // packed fp16 h write (B-ready ci-pair words)
        uint32_t hw[8];
        #pragma unroll
        for (int p = 0; p < 8; p++) hw[p] = packh2(hn2[0][p], hn2[1][p]);
        uint32_t* hp = hpout + (size_t)qout * NPIX + yx0;
        *(uint4*)(hp)     = *(uint4*)(hw);
        *(uint4*)(hp + 4) = *(uint4*)(hw + 4);

        // ---- arrive: step t done for this CTA ----
        __syncthreads();               // all epilogue stores issued CTA-wide
        __threadfence();               // make h globally visible (release)
        if (tid == 0) atomicAdd(&g_sync[dir][n][t], 1);
    }
}

// ---------------------------------------------------------------------------
extern "C" void kernel_launch(void* const* d_in, const int* in_sizes, int n_in,
                              void* d_out, int out_size)
{
    const float* x      = (const float*)d_in[0];
    const float* w_ih_f = (const float*)d_in[1];
    const float* w_hh_f = (const float*)d_in[2];
    const float* b_f    = (const float*)d_in[3];
    const float* w_ih_b = (const float*)d_in[4];
    const float* w_hh_b = (const float*)d_in[5];
    const float* b_b    = (const float*)d_in[6];
    float* out = (float*)d_out;

    cudaFuncSetAttribute(lstm_persistent, cudaFuncAttributeMaxDynamicSharedMemorySize,
                         (int)SMEM_STEP);

    zero_sync_kernel<<<1, 256>>>();
    prep_w_kernel<<<848, 256>>>(w_ih_f, w_hh_f, w_ih_b, w_hh_b);
    lstm_persistent<<<256, 256, SMEM_STEP>>>(x, b_f, b_b, out);
}

// round 14
// speedup vs baseline: 1.2145x; 1.0554x over previous
#include <cuda_runtime.h>
#include <cuda_fp16.h>
#include <cstdint>
#include <cstddef>

// ---------------- problem constants ----------------
constexpr int BB   = 8;
constexpr int TT   = 16;
constexpr int HID  = 64;
constexpr int NPIX = 1024;

// ---------------- step-kernel smem layout (uint32 words) ----------------
// Bh: word = hx*36 + cc*8 + kc*2 + h   (hx = halo px 0..379, 10 rows x 38 cols)
constexpr int BH_PXSTR = 36;                  // 32 data + 4 pad -> conflict-free LDS.128
constexpr int BH_W     = 380 * BH_PXSTR;      // 13680
constexpr int BX_OFF   = BH_W;                // Bx: [416 px][2 words] (380 real + zero pad)
constexpr int BX_PX    = 416;                 // covers max overread px 413 (zero-weight taps)
constexpr int BX_W     = BX_PX * 2;           // 832
constexpr int SGST     = 132;                 // epilogue gate staging stride (floats)
constexpr int SG_W     = 128 * SGST;          // 16896 (aliases Bh+Bx)
constexpr int SMEM_W   = SG_W;                // 16896 words
constexpr size_t SMEM_STEP = (size_t)SMEM_W * 4;   // 67584 B (x2 CTAs fits)

// chunk stream: 0..12 input (13..15 zero pad), 16.. hidden (16 + j*4 + kc)
constexpr int NG_FULL = 53;                   // 4 input groups + 49 hidden groups
constexpr int G_HID0  = 4;

// tap pixel offsets: poff[j] = (j/7)*38 + j%7
__device__ __constant__ int c_poff[52] = {
      0,  1,  2,  3,  4,  5,  6,
     38, 39, 40, 41, 42, 43, 44,
     76, 77, 78, 79, 80, 81, 82,
    114,115,116,117,118,119,120,
    152,153,154,155,156,157,158,
    190,191,192,193,194,195,196,
    228,229,230,231,232,233,234,
    266,267,268};

// ---------------- device scratch ----------------
__device__ uint32_t g_hp[2][(size_t)16 * 32 * NPIX];   // packed fp16 hidden (half2 ci-pairs)
__device__ float    g_c[(size_t)16 * HID * NPIX];      // cell state fp32
__device__ uint32_t g_wS[(size_t)4 * 240 * 1024];      // unified A chunk stream (frag order)
__device__ int      g_sync[2][8][8][16];               // per-(dir,n,rowblk,t), target 2

// ---------------- helpers ----------------
__device__ __forceinline__ void mma_f16(float* c, const uint32_t* a,
                                        uint32_t b0, uint32_t b1) {
    asm volatile(
        "mma.sync.aligned.m16n8k16.row.col.f32.f16.f16.f32 "
        "{%0,%1,%2,%3}, {%4,%5,%6,%7}, {%8,%9}, {%0,%1,%2,%3};"
        : "+f"(c[0]), "+f"(c[1]), "+f"(c[2]), "+f"(c[3])
        : "r"(a[0]), "r"(a[1]), "r"(a[2]), "r"(a[3]), "r"(b0), "r"(b1));
}
__device__ __forceinline__ uint32_t packh2(float lo, float hi) {
    __half2 h = __floats2half2_rn(lo, hi);
    return *(uint32_t*)&h;
}
__device__ __forceinline__ float sigf(float x) {
    return __fdividef(1.0f, 1.0f + __expf(-x));
}
__device__ __forceinline__ float tanh_fast(float x) {
    return __fdividef(2.0f, 1.0f + __expf(-2.0f * x)) - 1.0f;
}

// ---------------------------------------------------------------------------
// Kernel 0a: zero the sync counters (fresh state for every graph replay).
// ---------------------------------------------------------------------------
__global__ void zero_sync_kernel() {
    int* p = (int*)g_sync;
    for (int i = threadIdx.x; i < 2 * 8 * 8 * 16; i += 256) p[i] = 0;
}

// ---------------------------------------------------------------------------
// Kernel 0b: build unified A chunk stream. grid 848 = dm(4) x chunk(212).
// ---------------------------------------------------------------------------
__global__ void prep_w_kernel(const float* __restrict__ wihf, const float* __restrict__ whhf,
                              const float* __restrict__ wihb, const float* __restrict__ whhb)
{
    int bid  = blockIdx.x;
    int c    = bid % 212;
    int dm   = bid / 212;
    int mblk = dm & 1, dir = dm >> 1;
    const float* wih = dir ? wihb : wihf;
    const float* whh = dir ? whhb : whhf;
    uint32_t* dst = g_wS + ((size_t)dm * 240 + c) * 1024;

    for (int i = threadIdx.x; i < 1024; i += 256) {
        int reg  = i & 3;
        int lane = (i >> 2) & 31;
        int mt   = i >> 7;
        int m    = mt * 16 + (lane >> 2) + (reg & 1) * 8;
        int co   = (m >> 5) * 64 + mblk * 32 + (m & 31);
        float lo = 0.0f, hi = 0.0f;
        if (c < 13) {                     // input chunks
            int pair = c * 8 + (lane & 3) + (reg >> 1) * 4;
            int j = pair >> 1, cip = pair & 1;
            if (j < 49) {
                int ky = j / 7, kx = j - ky * 7;
                int ci0 = cip * 2;
                lo = wih[((size_t)co * 3 + ci0) * 49 + ky * 7 + kx];
                if (ci0 + 1 < 3)
                    hi = wih[((size_t)co * 3 + ci0 + 1) * 49 + ky * 7 + kx];
            }
        } else if (c >= 16) {             // hidden chunks
            int hc = c - 16;
            int j = hc >> 2, kc = hc & 3;
            if (j < 49) {
                int ky = j / 7, kx = j - ky * 7;
                int k = kc * 16 + (lane & 3) * 2 + (reg >> 1) * 8;
                lo = whh[((size_t)co * HID + k)     * 49 + ky * 7 + kx];
                hi = whh[((size_t)co * HID + k + 1) * 49 + ky * 7 + kx];
            }
        }
        dst[i] = packh2(lo, hi);
    }
}

// ---------------------------------------------------------------------------
// Kernel 1: PERSISTENT fused recurrence with HALO-GRANULARITY sync.
// A CTA at step t only waits for row-blocks rb-1, rb, rb+1 of its chain at
// step t-1 (2 arrivals each = both mblk CTAs) -> pipelined wavefront.
// grid 256 = rb(8) x mblk(2) x n(8) x dir(2); 256 threads; 2 CTAs/SM.
// ---------------------------------------------------------------------------
__global__ void __launch_bounds__(256, 2)
lstm_persistent(const float* __restrict__ x,
                const float* __restrict__ bf, const float* __restrict__ bb,
                float* __restrict__ out)
{
    extern __shared__ char smem[];
    uint32_t* smw = (uint32_t*)smem;

    int tid = threadIdx.x, wid = tid >> 5, lane = tid & 31;
    int rr = lane >> 2, cc = lane & 3;
    int wm = wid & 1, wn = wid >> 1;          // wn = output row 0..3

    int bid  = blockIdx.x;
    int rb   = bid & 7;
    int mblk = (bid >> 3) & 1;
    int n    = (bid >> 4) & 7;
    int dir  = (bid >> 7) & 1;
    int y0   = rb * 4;
    int dm   = dir * 2 + mblk;
    int dn   = dir * BB + n;

    float*       cbuf = g_c + (size_t)dn * HID * NPIX;
    const float* bias = dir ? bb : bf;

    // per-thread A fragment base (uint4 units): chunk c at Adm + c*256 + ms*32
    const uint4* Adm = (const uint4*)g_wS + (size_t)dm * 240 * 256 + wm * 128 + lane;

    int pbh = wn * 38 + rr;               // halo pixel base
    int bxb = BX_OFF + pbh * 2 + (cc & 1);

    volatile int* syncbase = &g_sync[dir][n][0][0];   // [rb][t], stride 16
    int rm = (rb > 0) ? rb - 1 : rb;
    int rp = (rb < 7) ? rb + 1 : rb;

    for (int t = 0; t < TT; t++) {
        int tcur = dir ? (TT - 1 - t) : t;
        const uint32_t* hpin  = g_hp[t & 1]       + (size_t)dn * 32 * NPIX;
        uint32_t*       hpout = g_hp[(t & 1) ^ 1] + (size_t)dn * 32 * NPIX;
        const float*    xin   = x + (size_t)(n * TT + tcur) * 3 * NPIX;

        float acc[4][4][4];
        #pragma unroll
        for (int ms = 0; ms < 4; ms++)
            #pragma unroll
            for (int ns = 0; ns < 4; ns++)
                #pragma unroll
                for (int q = 0; q < 4; q++) acc[ms][ns][q] = 0.0f;

        // ---- stage Bx (no h dependency): 10x38 halo of x, zero-pad to 416 ----
        #pragma unroll
        for (int i = 0; i < 2; i++) {
            int px = tid + i * 256;
            if (px < BX_PX) {
                float v0 = 0, v1 = 0, v2 = 0;
                if (px < 380) {
                    int row = px / 38, col = px - row * 38;
                    int y = y0 - 3 + row, xx = col - 3;
                    if ((unsigned)y < 32u && (unsigned)xx < 32u) {
                        int o = y * 32 + xx;
                        v0 = xin[o]; v1 = xin[NPIX + o]; v2 = xin[2 * NPIX + o];
                    }
                }
                smw[BX_OFF + px * 2]     = packh2(v0, v1);
                smw[BX_OFF + px * 2 + 1] = packh2(v2, 0.0f);
            }
        }

        // ---- wait for the 3 neighbor row-blocks to finish step t-1 ----
        if (t > 0) {
            if (tid == 0) { while (syncbase[rm * 16 + (t - 1)] < 2) { } }
            if (tid == 1) { while (syncbase[rb * 16 + (t - 1)] < 2) { } }
            if (tid == 2) { while (syncbase[rp * 16 + (t - 1)] < 2) { } }
            __syncthreads();
            __threadfence();   // acquire: neighbor h writes now visible

            // ---- stage Bh: thread = (q 0..15, t16); planes q and q+16 ----
            int q = tid >> 4, t16 = tid & 15;
            int offa = (q & 3) * 8 + (q >> 3) * 2 + ((q >> 2) & 1);  // q = kc*8+cc+4h
            const uint32_t* s0 = hpin + (size_t)q * NPIX;
            const uint32_t* s1 = hpin + (size_t)(q + 16) * NPIX;
            #pragma unroll 4
            for (int i = 0; i < 24; i++) {
                int hx = t16 + i * 16;
                if (hx < 380) {
                    int row = hx / 38, col = hx - row * 38;
                    int y = y0 - 3 + row, xx = col - 3;
                    uint32_t w0 = 0, w1 = 0;
                    if ((unsigned)y < 32u && (unsigned)xx < 32u) {
                        int o = y * 32 + xx;
                        w0 = s0[o]; w1 = s1[o];
                    }
                    smw[hx * BH_PXSTR + offa]     = w0;   // kc
                    smw[hx * BH_PXSTR + offa + 4] = w1;   // kc+2
                }
            }
        }
        __syncthreads();          // staging complete

        int nG = (t > 0) ? NG_FULL : 4;
        for (int gi = 0; gi < nG; gi++) {
            if (gi >= G_HID0) {
                // ---- hidden group: one tap j, 4 kc chunks; A via direct LDG ----
                int j = gi - G_HID0;
                const uint4* Ag = Adm + (16 + j * 4) * 256;
                int base = (pbh + c_poff[j]) * BH_PXSTR + cc * 8;
                uint4 b0[4], b1[4];
                #pragma unroll
                for (int ns = 0; ns < 4; ns++) {
                    b0[ns] = *(const uint4*)(smw + base + ns * (8 * BH_PXSTR));
                    b1[ns] = *(const uint4*)(smw + base + ns * (8 * BH_PXSTR) + 4);
                }
                #pragma unroll
                for (int kc = 0; kc < 4; kc++) {
                    uint4 a4[4];
                    #pragma unroll
                    for (int ms = 0; ms < 4; ms++)
                        a4[ms] = __ldg(Ag + kc * 256 + ms * 32);
                    #pragma unroll
                    for (int ms = 0; ms < 4; ms++) {
                        #pragma unroll
                        for (int ns = 0; ns < 4; ns++) {
                            uint32_t w0, w1;
                            if (kc == 0)      { w0 = b0[ns].x; w1 = b0[ns].y; }
                            else if (kc == 1) { w0 = b0[ns].z; w1 = b0[ns].w; }
                            else if (kc == 2) { w0 = b1[ns].x; w1 = b1[ns].y; }
                            else              { w0 = b1[ns].z; w1 = b1[ns].w; }
                            mma_f16(acc[ms][ns], (const uint32_t*)&a4[ms], w0, w1);
                        }
                    }
                }
            } else {
                // ---- input group: chunks ic = gi*4+u, 13 real total ----
                int icb = gi * 4;
                int cnt = 13 - icb; if (cnt > 4) cnt = 4;
                for (int u = 0; u < cnt; u++) {
                    int ic = icb + u;
                    const uint4* Ag = Adm + ic * 256;
                    int jb = ic * 4 + (cc >> 1);
                    int o1 = bxb + c_poff[jb] * 2;
                    int o2 = bxb + c_poff[jb + 2] * 2;
                    uint32_t b[4][2];
                    #pragma unroll
                    for (int ns = 0; ns < 4; ns++) {
                        b[ns][0] = smw[o1 + ns * 16];
                        b[ns][1] = smw[o2 + ns * 16];
                    }
                    #pragma unroll
                    for (int ms = 0; ms < 4; ms++) {
                        uint4 a4 = __ldg(Ag + ms * 32);
                        #pragma unroll
                        for (int ns = 0; ns < 4; ns++)
                            mma_f16(acc[ms][ns], (const uint32_t*)&a4, b[ns][0], b[ns][1]);
                    }
                }
            }
        }
        __syncthreads();

        // ---- acc -> s_g gate staging (aliases Bh/Bx space) ----
        float* sg = (float*)smem;
        #pragma unroll
        for (int ms = 0; ms < 4; ms++) {
            int m = wm * 64 + ms * 16 + rr;
            #pragma unroll
            for (int ns = 0; ns < 4; ns++) {
                int nn = wn * 32 + ns * 8 + 2 * cc;
                *(float2*)(sg + m * SGST + nn)       = make_float2(acc[ms][ns][0], acc[ms][ns][1]);
                *(float2*)(sg + (m + 8) * SGST + nn) = make_float2(acc[ms][ns][2], acc[ms][ns][3]);
            }
        }
        __syncthreads();

        // ---- LSTM epilogue: thread = (hid pair, 8 px), all vector ops ----
        int hl2 = tid >> 4;                   // 0..15 pair index
        int px0 = (tid & 15) * 8;             // 0..120
        int qout = mblk * 16 + hl2;
        int yx0  = y0 * 32 + px0;

        float hn2[2][8];
        #pragma unroll
        for (int e = 0; e < 2; e++) {
            int hl  = 2 * hl2 + e;
            int ch  = mblk * 32 + hl;
            float bi  = bias[0 * HID + ch];
            float bfg = bias[1 * HID + ch];
            float bg  = bias[2 * HID + ch];
            float bo  = bias[3 * HID + ch];
            const float* rI = sg + (0 * 32 + hl) * SGST + px0;
            const float* rF = sg + (1 * 32 + hl) * SGST + px0;
            const float* rG = sg + (2 * 32 + hl) * SGST + px0;
            const float* rO = sg + (3 * 32 + hl) * SGST + px0;
            float* cp_ptr = cbuf + (size_t)ch * NPIX + yx0;
            float* op     = out + ((size_t)((n * TT + tcur) * 2 * HID) + dir * HID + ch) * NPIX + yx0;
            #pragma unroll
            for (int v = 0; v < 2; v++) {
                float4 gI = *(const float4*)(rI + v * 4);
                float4 gF = *(const float4*)(rF + v * 4);
                float4 gG = *(const float4*)(rG + v * 4);
                float4 gO = *(const float4*)(rO + v * 4);
                float4 cv = make_float4(0, 0, 0, 0);
                if (t > 0) cv = *(const float4*)(cp_ptr + v * 4);
                float ig[4] = {gI.x + bi,  gI.y + bi,  gI.z + bi,  gI.w + bi};
                float fg[4] = {gF.x + bfg, gF.y + bfg, gF.z + bfg, gF.w + bfg};
                float gg[4] = {gG.x + bg,  gG.y + bg,  gG.z + bg,  gG.w + bg};
                float og[4] = {gO.x + bo,  gO.y + bo,  gO.z + bo,  gO.w + bo};
                float cold[4] = {cv.x, cv.y, cv.z, cv.w};
                float4 cnew, hnew;
                float* cn4 = (float*)&cnew;
                float* hn4 = (float*)&hnew;
                #pragma unroll
                for (int p = 0; p < 4; p++) {
                    float cn = sigf(fg[p]) * cold[p] + sigf(ig[p]) * tanh_fast(gg[p]);
                    float hn = sigf(og[p]) * tanh_fast(cn);
                    cn4[p] = cn;
                    hn4[p] = hn;
                    hn2[e][v * 4 + p] = hn;
                }
                *(float4*)(cp_ptr + v * 4) = cnew;
                *(float4*)(op + v * 4)     = hnew;
            }
        }
        // packed fp16 h write (B-ready ci-pair words)
        uint32_t hw[8];
        #pragma unroll
        for (int p = 0; p < 8; p++) hw[p] = packh2(hn2[0][p], hn2[1][p]);
        uint32_t* hp = hpout + (size_t)qout * NPIX + yx0;
        *(uint4*)(hp)     = *(uint4*)(hw);
        *(uint4*)(hp + 4) = *(uint4*)(hw + 4);

        // ---- arrive: row-block rb, step t done for this CTA (one of 2) ----
        __syncthreads();               // all epilogue stores issued CTA-wide
        __threadfence();               // make h globally visible (release)
        if (tid == 0) atomicAdd(&g_sync[dir][n][rb][t], 1);
    }
}

// ---------------------------------------------------------------------------
extern "C" void kernel_launch(void* const* d_in, const int* in_sizes, int n_in,
                              void* d_out, int out_size)
{
    const float* x      = (const float*)d_in[0];
    const float* w_ih_f = (const float*)d_in[1];
    const float* w_hh_f = (const float*)d_in[2];
    const float* b_f    = (const float*)d_in[3];
    const float* w_ih_b = (const float*)d_in[4];
    const float* w_hh_b = (const float*)d_in[5];
    const float* b_b    = (const float*)d_in[6];
    float* out = (float*)d_out;

    cudaFuncSetAttribute(lstm_persistent, cudaFuncAttributeMaxDynamicSharedMemorySize,
                         (int)SMEM_STEP);

    zero_sync_kernel<<<1, 256>>>();
    prep_w_kernel<<<848, 256>>>(w_ih_f, w_hh_f, w_ih_b, w_hh_b);
    lstm_persistent<<<256, 256, SMEM_STEP>>>(x, b_f, b_b, out);
}